// round 8
// baseline (speedup 1.0000x reference)
#include <cuda_runtime.h>
#include <math.h>

#define MM    16
#define TT    512
#define DD    512
#define HH    512
#define QKN   256
#define KACT  4
#define NG    148
#define TPB   512
#define NWARP (TPB/32)              // 16
#define GWARPS (NG*NWARP)           // 2368
#define NTHREADS (NG*TPB)           // 75776
#define DYNSM 49152

#define DOT4(s,a,b) { s=fmaf((a).x,(b).x,s); s=fmaf((a).y,(b).y,s); \
                      s=fmaf((a).z,(b).z,s); s=fmaf((a).w,(b).w,s); }

// ---------------- persistent scratch ----------------
__device__ __align__(16) float g_h  [MM*HH];
__device__ __align__(16) float g_c  [MM*HH];
__device__ __align__(16) float g_q  [MM*QKN];
__device__ __align__(16) float g_th [MM*HH];
__device__ __align__(16) float g_q2p[2][MM*HH];   // pair partials (h-halves)
__device__ __align__(16) float g_k2p[2][MM*HH];
__device__ __align__(16) float g_v2p[2][MM*HH];
__device__ __align__(16) float g_kxAll[(size_t)TT*MM*QKN]; // 8 MB: key_x+bk all t
__device__ __align__(16) float g_v1All[(size_t)TT*MM*DD];  // 16 MB: val1+bv all t
__device__ volatile unsigned g_arr[NG];
__device__ volatile unsigned g_rel;

// ---------------- helpers ----------------
__device__ __forceinline__ float warp_reduce(float s) {
#pragma unroll
  for (int o = 16; o; o >>= 1) s += __shfl_xor_sync(0xffffffffu, s, o);
  return s;
}
__device__ __forceinline__ float sigf(float x) { return 1.f / (1.f + expf(-x)); }

template<int N4, bool ACG, bool BCG>
__device__ __forceinline__ float wdot(const float* __restrict__ A,
                                      const float* __restrict__ B, int lane) {
  const float4* a4 = (const float4*)A;
  const float4* b4 = (const float4*)B;
  float s = 0.f;
#pragma unroll
  for (int k = 0; k < N4; k++) {
    int idx = lane + 32 * k;
    float4 a = ACG ? __ldcg(a4 + idx) : __ldg(a4 + idx);
    float4 b = BCG ? __ldcg(b4 + idx) : __ldg(b4 + idx);
    DOT4(s, a, b);
  }
  return warp_reduce(s);
}

__device__ __forceinline__ float sdot512(const float* a, const float* b, int lane) {
  float s = 0.f;
#pragma unroll
  for (int k = 0; k < 4; k++) {
    float4 av = ((const float4*)a)[lane + 32 * k];
    float4 bv = ((const float4*)b)[lane + 32 * k];
    DOT4(s, av, bv);
  }
  return warp_reduce(s);
}

// CTA-cooperative transposed-GEMV half: dst[0..127] = sum_{h in half hh}
// vec[h]*W[h*HH + qt*128 + o].  16 warps x 16 rows, smem reduce. All loads hoisted.
__device__ __forceinline__ void cta_tgemv(const float* __restrict__ W,
                                          const float* __restrict__ vec,
                                          float* __restrict__ dst,
                                          int qt, int hh, float* s_red) {
  const int lane = threadIdx.x & 31, warp = threadIdx.x >> 5;
  const int h0 = hh * 256 + warp * 16;
  const float4* vp = (const float4*)(vec + h0);
  float4 tv0 = __ldcg(vp + 0), tv1 = __ldcg(vp + 1);
  float4 tv2 = __ldcg(vp + 2), tv3 = __ldcg(vp + 3);
  const float* base = W + (size_t)h0 * HH + qt * 128;
  float4 w[16];
#pragma unroll
  for (int r = 0; r < 16; r++)
    w[r] = __ldg((const float4*)(base + (size_t)r * HH) + lane);
  float tvs[16] = {tv0.x,tv0.y,tv0.z,tv0.w, tv1.x,tv1.y,tv1.z,tv1.w,
                   tv2.x,tv2.y,tv2.z,tv2.w, tv3.x,tv3.y,tv3.z,tv3.w};
  float4 acc = make_float4(0.f, 0.f, 0.f, 0.f);
#pragma unroll
  for (int r = 0; r < 16; r++) {
    float tsc = tvs[r];
    acc.x = fmaf(tsc, w[r].x, acc.x); acc.y = fmaf(tsc, w[r].y, acc.y);
    acc.z = fmaf(tsc, w[r].z, acc.z); acc.w = fmaf(tsc, w[r].w, acc.w);
  }
  ((float4*)s_red)[warp * 32 + lane] = acc;
  __syncthreads();
  if (threadIdx.x < 128) {
    float s = 0.f;
#pragma unroll
    for (int wgi = 0; wgi < 16; wgi++) s += s_red[wgi * 128 + threadIdx.x];
    __stcg(dst + threadIdx.x, s);
  }
  __syncthreads();
}

// Flag-based grid barrier: parallel arrivals, CTA0-warp0 aggregates, one release word.
__device__ __forceinline__ void gbar(unsigned lgen) {
  __syncthreads();
  if (threadIdx.x == 0) { __threadfence(); g_arr[blockIdx.x] = lgen; }
  if (blockIdx.x == 0 && threadIdx.x < 32) {
    bool mine;
    do {
      mine = true;
      for (int s = threadIdx.x; s < NG; s += 32)
        if (g_arr[s] != lgen) mine = false;
    } while (!__all_sync(0xffffffffu, mine));
    if (threadIdx.x == 0) { __threadfence(); g_rel = lgen; }
  }
  if (threadIdx.x == 0) {
    while (g_rel != lgen) { }
    __threadfence();
  }
  __syncthreads();
}

// ---------------- main persistent kernel ----------------
__global__ void __launch_bounds__(TPB, 1)
rim_kernel(const float* __restrict__ inputs,
           const float* __restrict__ Wq,  const float* __restrict__ bq,
           const float* __restrict__ Wk,  const float* __restrict__ bk,
           const float* __restrict__ Wv,  const float* __restrict__ bv,
           const float* __restrict__ W_ih, const float* __restrict__ b_ih,
           const float* __restrict__ W_hh, const float* __restrict__ b_hh,
           const float* __restrict__ Wqg, const float* __restrict__ Wkg,
           const float* __restrict__ Wvg,
           float* __restrict__ out, int outTotal) {
  const int lane = threadIdx.x & 31;
  const int warp = threadIdx.x >> 5;
  const int gw   = blockIdx.x * NWARP + warp;
  const int gt   = blockIdx.x * TPB + threadIdx.x;

  __shared__ float s_att0[MM], s_att1[MM], s_l0[MM];
  __shared__ int   s_act[KACT], s_slot[MM], s_dirty[MM], s_inact[MM - KACT], s_nDirty;
  __shared__ unsigned char s_isDirty[MM];
  __shared__ float s_s[KACT * MM], s_w[KACT * MM];
  extern __shared__ __align__(16) char dynsm[];
  float* s_k2b = (float*)dynsm;               // 32KB (E)
  float* s_q2b = (float*)(dynsm + 32768);     // 8KB  (E)
  float* s_sel = (float*)(dynsm + 40960);     // 8KB  (B)
  float* s_red = (float*)(dynsm + 40960);     // 8KB  (A,C; aliases s_sel)
  float (*sA)[32]   = (float(*)[32])dynsm;            // precompute
  float (*sBT)[129] = (float(*)[129])(dynsm + 8192);  // precompute

  unsigned lgen = g_rel + 1;                  // continues across graph replays

  // ======== One-time precompute: kxAll = Wk@x+bk, v1All = Wv@x+bv (tiled GEMM) ========
  {
    const int NKXT = MM * (QKN / 64) * (TT / 128);       // 256
    const int NTOT = NKXT + MM * (DD / 64) * (TT / 128); // 768
    const int ti = threadIdx.x >> 6;
    const int tt = threadIdx.x & 63;
    for (int tile = blockIdx.x; tile < NTOT; tile += NG) {
      int m, i0, t0, iN;
      const float* W; const float* bias; float* dst;
      if (tile < NKXT) {
        m = tile >> 4;
        int r = tile & 15; i0 = (r >> 2) * 64; t0 = (r & 3) * 128;
        W = Wk + (size_t)m * QKN * DD; bias = bk + m * QKN; iN = QKN; dst = g_kxAll;
      } else {
        int tl = tile - NKXT;
        m = tl >> 5;
        int r = tl & 31; i0 = (r >> 2) * 64; t0 = (r & 3) * 128;
        W = Wv + (size_t)m * DD * DD; bias = bv + m * DD; iN = DD; dst = g_v1All;
      }
      const float* X = inputs + (size_t)m * TT * DD;
      float acc0[8], acc1[8];
#pragma unroll
      for (int r8 = 0; r8 < 8; r8++) { acc0[r8] = 0.f; acc1[r8] = 0.f; }
      for (int kc = 0; kc < DD; kc += 32) {
        __syncthreads();
        {
          int ar = threadIdx.x >> 3, ac4 = threadIdx.x & 7;
          float4 v = __ldg((const float4*)(W + (size_t)(i0 + ar) * DD + kc) + ac4);
          *(float4*)&sA[ar][ac4 * 4] = v;
        }
        {
#pragma unroll
          for (int j = 0; j < 2; j++) {
            int idx = threadIdx.x * 2 + j;
            int xr = idx >> 3, xc4 = idx & 7;
            float4 v = __ldg((const float4*)(X + (size_t)(t0 + xr) * DD + kc) + xc4);
            sBT[xc4 * 4 + 0][xr] = v.x; sBT[xc4 * 4 + 1][xr] = v.y;
            sBT[xc4 * 4 + 2][xr] = v.z; sBT[xc4 * 4 + 3][xr] = v.w;
          }
        }
        __syncthreads();
#pragma unroll
        for (int k = 0; k < 32; k++) {
          float b0 = sBT[k][tt], b1 = sBT[k][tt + 64];
#pragma unroll
          for (int r8 = 0; r8 < 8; r8++) {
            float a = sA[ti * 8 + r8][k];
            acc0[r8] = fmaf(a, b0, acc0[r8]);
            acc1[r8] = fmaf(a, b1, acc1[r8]);
          }
        }
      }
      __syncthreads();
#pragma unroll
      for (int j = 0; j < 2; j++) {
        int tcur = t0 + tt + j * 64;
        float* drow = dst + ((size_t)tcur * MM + m) * iN + i0 + ti * 8;
        float* ac = j ? acc1 : acc0;
#pragma unroll
        for (int r8 = 0; r8 < 8; r8++)
          drow[r8] = ac[r8] + __ldg(bias + i0 + ti * 8 + r8);
      }
    }
  }
  for (int e = gt; e < MM * HH; e += NTHREADS) { g_h[e] = 0.f; g_c[e] = 0.f; }
  if (threadIdx.x == 0) {
    s_nDirty = MM;
    for (int j = 0; j < MM; j++) { s_dirty[j] = j; s_isDirty[j] = 1; }
  }
  gbar(lgen); lgen++;

  const float scale = 1.f / 16.f;

  for (int t = 0; t < TT; ++t) {
    const int nD = s_nDirty;

    // ==== Phase A: dirty k2/v2 (CTA tasks, pair-partials) + dirty q dots ====
    {
      int nCT = nD * 16;                       // (di, mat, qt, hh)
      for (int ct = blockIdx.x; ct < nCT; ct += NG) {
        int di = ct >> 4, r = ct & 15;
        int mat = r >> 3, qt = (r >> 1) & 3, hh = r & 1;
        int m = s_dirty[di];
        const float* W = (mat ? Wvg : Wkg) + (size_t)m * HH * HH;
        float* dst = (mat ? g_v2p : g_k2p)[hh] + m * HH + qt * 128;
        cta_tgemv(W, g_h + m * HH, dst, qt, hh, s_red);
      }
      if (blockIdx.x >= 64) {
        int gw2 = (blockIdx.x - 64) * NWARP + warp;
        for (int task = gw2; task < nD * QKN; task += 84 * NWARP) {
          int di = task >> 8, i = task & 255;
          int m = s_dirty[di];
          float qv = wdot<4, false, true>(Wq + ((size_t)m * QKN + i) * HH,
                                          g_h + m * HH, lane);
          if (lane == 0) g_q[m * QKN + i] = qv + __ldg(bq + m * QKN + i);
        }
      }
    }
    gbar(lgen); lgen++;

    // ==== Phase B: logits/topk/sel (per-CTA) + LSTM (interleaved loads) ====
    if (warp < MM) {
      int m = warp;
      float l1 = wdot<2, true, false>(g_q + m * QKN,
                                      g_kxAll + ((size_t)t * MM + m) * QKN, lane);
      float l0 = 0.f;
      if (s_isDirty[m])
        l0 = wdot<2, true, false>(g_q + m * QKN, bk + m * QKN, lane);
      if (lane == 0) {
        if (s_isDirty[m]) s_l0[m] = l0 * scale;
        float L0 = s_l0[m], L1 = l1 * scale;
        float mx = fmaxf(L0, L1);
        float e0 = expf(L0 - mx), e1 = expf(L1 - mx);
        float inv = 1.f / (e0 + e1);
        s_att0[m] = e0 * inv; s_att1[m] = e1 * inv;
      }
    }
    __syncthreads();
    if (threadIdx.x == 0) {
      bool used[MM];
#pragma unroll
      for (int j = 0; j < MM; j++) used[j] = false;
      for (int k = 0; k < KACT; k++) {
        int best = 0; float bvv = 3.402823466e38f;
        for (int j = 0; j < MM; j++)
          if (!used[j] && s_att0[j] < bvv) { bvv = s_att0[j]; best = j; }
        used[best] = true; s_act[k] = best;
        if (blockIdx.x == 0 && outTotal >= TT * MM * HH + TT * KACT)
          out[(size_t)TT * MM * HH + (size_t)t * KACT + k] = (float)best;
      }
      for (int j = 0; j < MM; j++) s_slot[j] = -1;
      for (int k = 0; k < KACT; k++) s_slot[s_act[k]] = k;
      int ii = 0;
      for (int j = 0; j < MM; j++) if (s_slot[j] < 0) s_inact[ii++] = j;
    }
    __syncthreads();
    for (int idx = threadIdx.x; idx < KACT * DD; idx += TPB) {
      int a = idx >> 9, r = idx & 511;
      int m = s_act[a];
      float v1 = __ldg(&g_v1All[((size_t)t * MM + m) * DD + r]);
      s_sel[idx] = s_att0[m] * __ldg(bv + m * DD + r) + s_att1[m] * v1;
    }
    __syncthreads();
    for (int task = gw; task < KACT * HH; task += GWARPS) {
      int a = task >> 9, j = task & 511;
      int m = s_act[a];
      const float4* selp = (const float4*)(s_sel + a * DD);
      const float4* hp   = (const float4*)(g_h + m * HH);
      float4 sb[4], hb[4];
#pragma unroll
      for (int k = 0; k < 4; k++) {
        sb[k] = selp[lane + 32 * k];
        hb[k] = __ldcg(hp + lane + 32 * k);
      }
      const float* Wi = W_ih + (size_t)m * 4 * HH * DD;
      const float* Wh = W_hh + (size_t)m * 4 * HH * HH;
      const float4* wiP0 = (const float4*)(Wi + (size_t)(0 * HH + j) * DD);
      const float4* wiP1 = (const float4*)(Wi + (size_t)(1 * HH + j) * DD);
      const float4* wiP2 = (const float4*)(Wi + (size_t)(2 * HH + j) * DD);
      const float4* wiP3 = (const float4*)(Wi + (size_t)(3 * HH + j) * DD);
      const float4* whP0 = (const float4*)(Wh + (size_t)(0 * HH + j) * HH);
      const float4* whP1 = (const float4*)(Wh + (size_t)(1 * HH + j) * HH);
      const float4* whP2 = (const float4*)(Wh + (size_t)(2 * HH + j) * HH);
      const float4* whP3 = (const float4*)(Wh + (size_t)(3 * HH + j) * HH);
      float s0 = 0.f, s1 = 0.f, s2 = 0.f, s3 = 0.f;
#pragma unroll
      for (int k = 0; k < 4; k++) {
        int idx = lane + 32 * k;
        float4 a0 = __ldg(wiP0 + idx), c0 = __ldg(whP0 + idx);
        float4 a1 = __ldg(wiP1 + idx), c1 = __ldg(whP1 + idx);
        float4 a2 = __ldg(wiP2 + idx), c2 = __ldg(whP2 + idx);
        float4 a3 = __ldg(wiP3 + idx), c3 = __ldg(whP3 + idx);
        DOT4(s0, a0, sb[k]); DOT4(s0, c0, hb[k]);
        DOT4(s1, a1, sb[k]); DOT4(s1, c1, hb[k]);
        DOT4(s2, a2, sb[k]); DOT4(s2, c2, hb[k]);
        DOT4(s3, a3, sb[k]); DOT4(s3, c3, hb[k]);
      }
      s0 = warp_reduce(s0); s1 = warp_reduce(s1);
      s2 = warp_reduce(s2); s3 = warp_reduce(s3);
      if (lane == 0) {
        float iv = s0 + __ldg(b_ih + m * 4 * HH + 0 * HH + j) + __ldg(b_hh + m * 4 * HH + 0 * HH + j);
        float fv = s1 + __ldg(b_ih + m * 4 * HH + 1 * HH + j) + __ldg(b_hh + m * 4 * HH + 1 * HH + j);
        float gg = s2 + __ldg(b_ih + m * 4 * HH + 2 * HH + j) + __ldg(b_hh + m * 4 * HH + 2 * HH + j);
        float ov = s3 + __ldg(b_ih + m * 4 * HH + 3 * HH + j) + __ldg(b_hh + m * 4 * HH + 3 * HH + j);
        float co = __ldcg(&g_c[m * HH + j]);
        float cn = sigf(fv) * co + sigf(iv) * tanhf(gg);
        float hn = sigf(ov) * tanhf(cn);
        __stcg(&g_c[m * HH + j], cn);
        __stcg(&g_th[m * HH + j], hn);
      }
    }
    for (int e = gt; e < MM * HH; e += NTHREADS) {
      if (s_slot[e >> 9] < 0) __stcg(&g_c[e], 0.f);
    }
    __syncthreads();
    if (threadIdx.x == 0) {
      s_nDirty = KACT;
      for (int k = 0; k < KACT; k++) s_dirty[k] = s_act[k];
      for (int j = 0; j < MM; j++) s_isDirty[j] = (s_slot[j] >= 0) ? 1 : 0;
    }
    gbar(lgen); lgen++;

    // ==== Phase C: active q2/k2/v2 from temp_h (96 CTA tasks) + inactive out ====
    for (int ct = blockIdx.x; ct < 96; ct += NG) {
      int a = ct / 24, r = ct % 24;
      int mat = r >> 3, qt = (r >> 1) & 3, hh = r & 1;
      int m = s_act[a];
      const float* W = (mat == 0 ? Wqg : (mat == 1 ? Wkg : Wvg)) + (size_t)m * HH * HH;
      float* dst = (mat == 0 ? g_q2p : (mat == 1 ? g_k2p : g_v2p))[hh] + m * HH + qt * 128;
      cta_tgemv(W, g_th + m * HH, dst, qt, hh, s_red);
    }
    if (blockIdx.x >= 96) {
      int base = (blockIdx.x - 96) * TPB + threadIdx.x;
      for (int e = base; e < (MM - KACT) * 128; e += 52 * TPB) {
        int m = s_inact[e >> 7], f4 = e & 127;
        float4 v = __ldcg((const float4*)g_h + m * 128 + f4);
        ((float4*)out)[(size_t)t * MM * 128 + m * 128 + f4] = v;
      }
    }
    gbar(lgen); lgen++;

    // ==== Phase E: att2 (per-CTA smem, pair-sum staging), new_h for active ====
    for (int idx = threadIdx.x; idx < KACT * HH; idx += TPB) {
      int a = idx >> 9, i = idx & 511;
      int m = s_act[a];
      s_q2b[idx] = __ldcg(&g_q2p[0][m * HH + i]) + __ldcg(&g_q2p[1][m * HH + i]);
    }
    for (int idx = threadIdx.x; idx < MM * HH; idx += TPB)
      s_k2b[idx] = __ldcg(&g_k2p[0][idx]) + __ldcg(&g_k2p[1][idx]);
    __syncthreads();
    for (int d6 = warp; d6 < KACT * MM; d6 += NWARP) {
      int a = d6 >> 4, j = d6 & 15;
      float s = sdot512(s_q2b + a * HH, s_k2b + j * HH, lane);
      if (lane == 0) s_s[d6] = s;
    }
    __syncthreads();
    if (threadIdx.x < KACT) {
      int a = threadIdx.x;
      float mx = -3.402823466e38f;
#pragma unroll
      for (int j = 0; j < MM; j++) mx = fmaxf(mx, s_s[a * MM + j]);
      float ev[MM]; float sum = 0.f;
#pragma unroll
      for (int j = 0; j < MM; j++) { ev[j] = expf(s_s[a * MM + j] - mx); sum += ev[j]; }
      float inv = 1.f / sum;
#pragma unroll
      for (int j = 0; j < MM; j++) s_w[a * MM + j] = ev[j] * inv;
    }
    __syncthreads();
    if (gw < KACT * 128) {                      // one warp per active float4 output
      int a = gw >> 7, f4 = gw & 127;
      int m = s_act[a];
      float4 acc = make_float4(0.f, 0.f, 0.f, 0.f);
      if (lane < MM) {
        float wj = s_w[a * MM + lane];
        float4 v0 = __ldcg((const float4*)g_v2p[0] + lane * 128 + f4);
        float4 v1 = __ldcg((const float4*)g_v2p[1] + lane * 128 + f4);
        acc.x = wj * (v0.x + v1.x); acc.y = wj * (v0.y + v1.y);
        acc.z = wj * (v0.z + v1.z); acc.w = wj * (v0.w + v1.w);
      }
#pragma unroll
      for (int o = 16; o; o >>= 1) {
        acc.x += __shfl_xor_sync(0xffffffffu, acc.x, o);
        acc.y += __shfl_xor_sync(0xffffffffu, acc.y, o);
        acc.z += __shfl_xor_sync(0xffffffffu, acc.z, o);
        acc.w += __shfl_xor_sync(0xffffffffu, acc.w, o);
      }
      if (lane == 0) {
        float4 th = __ldcg((const float4*)g_th + m * 128 + f4);
        float4 val = make_float4(acc.x + th.x, acc.y + th.y,
                                 acc.z + th.z, acc.w + th.w);
        __stcg((float4*)g_h + m * 128 + f4, val);
        ((float4*)out)[(size_t)t * MM * 128 + m * 128 + f4] = val;
      }
    }
    gbar(lgen); lgen++;
  }
}

// ---------------- launch ----------------
extern "C" void kernel_launch(void* const* d_in, const int* in_sizes, int n_in,
                              void* d_out, int out_size) {
  (void)in_sizes; (void)n_in;
  cudaFuncSetAttribute(rim_kernel, cudaFuncAttributeMaxDynamicSharedMemorySize, DYNSM);
  rim_kernel<<<NG, TPB, DYNSM>>>(
      (const float*)d_in[0],  (const float*)d_in[1],  (const float*)d_in[2],
      (const float*)d_in[3],  (const float*)d_in[4],  (const float*)d_in[5],
      (const float*)d_in[6],  (const float*)d_in[7],  (const float*)d_in[8],
      (const float*)d_in[9],  (const float*)d_in[10], (const float*)d_in[11],
      (const float*)d_in[12], (const float*)d_in[13],
      (float*)d_out, out_size);
}